// round 6
// baseline (speedup 1.0000x reference)
#include <cuda_runtime.h>
#include <math.h>

// Problem: tensor [8192, 256] fp32.
// out = (adj @ X) where adj = rownorm(cosine_sim(X)).
// Factored: M = X_hat^T X (256x256, SYMMETRIC), s = sum_j x_hat_j (256),
//           out[i] = (x_i @ M) / (x_i . s)   (inv-norm cancels).
// Denominator in compensated fp32 (Dot2) -- fp64-grade accuracy w/o the
// de-rated FP64 pipe. GEMM mainloops use packed fma.rn.f32x2 (FFMA2): 2x the
// scalar FFMA roofline on sm_103a.

#define NROWS 8192
#define DDIM  256
#define GCHUNKS 32          // gram K-chunks: 256 rows each
#define SCHUNKS 256         // norm/s blocks: 32 rows each
#define NTILES  10          // upper-triangle 64x64 tiles of the 4x4 tile grid

typedef unsigned long long ull;

__device__ float  g_invn[NROWS];
__device__ float2 g_spart[SCHUNKS][DDIM];
__device__ float2 g_s2[DDIM];
__device__ float  g_rinv[NROWS];
__device__ float  g_Mpart[GCHUNKS][NTILES][64 * 64];
__device__ float  g_M[DDIM * DDIM];

__device__ const int c_TI[NTILES] = {0,0,0,0,1,1,1,2,2,3};
__device__ const int c_TJ[NTILES] = {0,1,2,3,1,2,3,2,3,3};

// ---- error-free fp32 transforms ------------------------------------------
__device__ __forceinline__ void twoSum(float a, float b, float& s, float& e) {
    s = a + b;
    float bb = s - a;
    e = (a - (s - bb)) + (b - bb);
}
__device__ __forceinline__ void twoProd(float a, float b, float& p, float& e) {
    p = a * b;
    e = fmaf(a, b, -p);
}

// ---- packed f32x2 helpers (sm_100+ PTX) -----------------------------------
__device__ __forceinline__ ull pack2(float lo, float hi) {
    ull r;
    asm("mov.b64 %0, {%1, %2};" : "=l"(r) : "f"(lo), "f"(hi));
    return r;
}
__device__ __forceinline__ ull dup2(float v) {
    ull r;
    asm("mov.b64 %0, {%1, %1};" : "=l"(r) : "f"(v));
    return r;
}
__device__ __forceinline__ void fma2(ull& d, ull a, ull b) {
    asm("fma.rn.f32x2 %0, %1, %2, %3;" : "=l"(d) : "l"(a), "l"(b), "l"(d));
}
__device__ __forceinline__ float2 unpack2(ull v) {
    float lo, hi;
    asm("mov.b64 {%0, %1}, %2;" : "=f"(lo), "=f"(hi) : "l"(v));
    return make_float2(lo, hi);
}

// ---------------------------------------------------------------------------
// Kernel 1: per-row inverse norms + compensated fp32 partial column sums of
// X_hat. 256 blocks x 256 threads; block b handles rows [b*32, +32).
// ---------------------------------------------------------------------------
__global__ void __launch_bounds__(256) k_norm_s(const float* __restrict__ X) {
    __shared__ float invn_sh[32];
    const int row0 = blockIdx.x * 32;
    const int wid  = threadIdx.x >> 5;
    const int lane = threadIdx.x & 31;

    for (int r = wid; r < 32; r += 8) {
        const float4* p = reinterpret_cast<const float4*>(X + (size_t)(row0 + r) * DDIM);
        float ss = 0.f;
        #pragma unroll
        for (int q = 0; q < 2; q++) {
            float4 v = p[lane + q * 32];
            ss += v.x * v.x + v.y * v.y + v.z * v.z + v.w * v.w;
        }
        #pragma unroll
        for (int o = 16; o > 0; o >>= 1) ss += __shfl_xor_sync(0xffffffffu, ss, o);
        if (lane == 0) {
            float inv = 1.0f / fmaxf(sqrtf(ss), 1e-8f);
            invn_sh[r]       = inv;
            g_invn[row0 + r] = inv;
        }
    }
    __syncthreads();

    const int t = threadIdx.x;
    float s = 0.f, c = 0.f;
    #pragma unroll
    for (int r = 0; r < 32; r++) {
        float p, e, t1;
        twoProd(invn_sh[r], X[(size_t)(row0 + r) * DDIM + t], p, e);
        twoSum(s, p, s, t1);
        c += t1 + e;
    }
    g_spart[blockIdx.x][t] = make_float2(s, c);
}

// ---------------------------------------------------------------------------
// Kernel 2: partial Gram, upper-triangle 64x64 tiles (M symmetric).
// grid = (32 k-chunks x 256 rows, 10 tiles). 256 threads, 4x4 per thread with
// j-pairs packed into f32x2. Double-buffered smem, one sync per 8-k stage.
// ---------------------------------------------------------------------------
__global__ void __launch_bounds__(256) k_gram(const float* __restrict__ X) {
    __shared__ float SA[2][8][64];
    __shared__ float SB[2][8][64];

    const int c  = blockIdx.x;
    const int t  = blockIdx.y;
    const int ti = c_TI[t];
    const int tj = c_TJ[t];
    const int tx = threadIdx.x & 15;
    const int ty = (threadIdx.x >> 4) & 15;
    const int side = threadIdx.x >> 7;          // 0: SA loader, 1: SB loader
    const int li   = (threadIdx.x >> 4) & 7;
    const int lf   = threadIdx.x & 15;
    const int rowbase = c * 256;
    const int colbase = (side == 0 ? ti : tj) * 64;

    ull T2[4][2];
    #pragma unroll
    for (int i = 0; i < 4; i++) { T2[i][0] = 0ull; T2[i][1] = 0ull; }

    // prologue: stage 0
    {
        const int gr = rowbase + li;
        float4 v = *reinterpret_cast<const float4*>(X + (size_t)gr * DDIM + colbase + lf * 4);
        if (side == 0) {
            const float sc = g_invn[gr];
            *reinterpret_cast<float4*>(&SA[0][li][lf * 4]) =
                make_float4(v.x * sc, v.y * sc, v.z * sc, v.w * sc);
        } else {
            *reinterpret_cast<float4*>(&SB[0][li][lf * 4]) = v;
        }
    }
    __syncthreads();

    for (int s = 0; s < 32; s++) {
        const int p = s & 1;
        float4 v;
        float sc = 1.f;
        if (s < 31) {
            const int gr = rowbase + (s + 1) * 8 + li;
            v = *reinterpret_cast<const float4*>(X + (size_t)gr * DDIM + colbase + lf * 4);
            if (side == 0) sc = g_invn[gr];
        }
        #pragma unroll
        for (int r = 0; r < 8; r++) {
            float4 a = *reinterpret_cast<const float4*>(&SA[p][r][ty * 4]);
            float4 b = *reinterpret_cast<const float4*>(&SB[p][r][tx * 4]);
            ull b01 = pack2(b.x, b.y);
            ull b23 = pack2(b.z, b.w);
            const float aa[4] = {a.x, a.y, a.z, a.w};
            #pragma unroll
            for (int i = 0; i < 4; i++) {
                ull ai = dup2(aa[i]);
                fma2(T2[i][0], ai, b01);
                fma2(T2[i][1], ai, b23);
            }
        }
        if (s < 31) {
            if (side == 0)
                *reinterpret_cast<float4*>(&SA[p ^ 1][li][lf * 4]) =
                    make_float4(v.x * sc, v.y * sc, v.z * sc, v.w * sc);
            else
                *reinterpret_cast<float4*>(&SB[p ^ 1][li][lf * 4]) = v;
        }
        __syncthreads();
    }

    float* out = &g_Mpart[c][t][0];
    #pragma unroll
    for (int i = 0; i < 4; i++) {
        float2 lo = unpack2(T2[i][0]);
        float2 hi = unpack2(T2[i][1]);
        *reinterpret_cast<float4*>(&out[(ty * 4 + i) * 64 + tx * 4]) =
            make_float4(lo.x, lo.y, hi.x, hi.y);
    }
}

// ---------------------------------------------------------------------------
// Kernel 3: compensated fp32 reduce of Mpart (with symmetric mirror) and the
// s-partial pairs. 160 blocks x 256 threads cover 10*4096 upper-tile elems.
// ---------------------------------------------------------------------------
__global__ void __launch_bounds__(256) k_reduce() {
    const int idx = blockIdx.x * 256 + threadIdx.x;   // 0..40959
    const int t = idx >> 12;
    const int e = idx & 4095;
    float s = 0.f, comp = 0.f;
    #pragma unroll
    for (int c = 0; c < GCHUNKS; c++) {
        float t1;
        twoSum(s, g_Mpart[c][t][e], s, t1);
        comp += t1;
    }
    const float v = s + comp;
    const int k = c_TI[t] * 64 + (e >> 6);
    const int l = c_TJ[t] * 64 + (e & 63);
    if (k < l) {
        g_M[k * DDIM + l] = v;
        g_M[l * DDIM + k] = v;
    } else if (k == l) {
        g_M[k * DDIM + l] = v;
    }

    if (blockIdx.x == 0) {
        float sa = 0.f, ca = 0.f;
        #pragma unroll 8
        for (int b = 0; b < SCHUNKS; b++) {
            float2 p = g_spart[b][threadIdx.x];
            float t1;
            twoSum(sa, p.x, sa, t1);
            ca += t1 + p.y;
        }
        g_s2[threadIdx.x] = make_float2(sa, ca);
    }
}

// ---------------------------------------------------------------------------
// Kernel 4: rinv[i] = 1 / (x_i . s) via fp32 Dot2, one row per warp,
// float4 global loads (2 LDG.128 per lane).
// ---------------------------------------------------------------------------
__global__ void __launch_bounds__(256) k_rinv(const float* __restrict__ X) {
    __shared__ float2 s_sh[DDIM];
    s_sh[threadIdx.x] = g_s2[threadIdx.x];
    __syncthreads();
    const int wid  = threadIdx.x >> 5;
    const int lane = threadIdx.x & 31;
    const int row  = blockIdx.x * 8 + wid;

    const float4* xp4 = reinterpret_cast<const float4*>(X + (size_t)row * DDIM);
    float s = 0.f, c = 0.f;
    #pragma unroll
    for (int q = 0; q < 2; q++) {
        const int f = lane + q * 32;          // float4 index 0..63
        const float4 xv = xp4[f];
        const float xs[4] = {xv.x, xv.y, xv.z, xv.w};
        #pragma unroll
        for (int m = 0; m < 4; m++) {
            const float2 sv = s_sh[f * 4 + m];
            float p, e, t1;
            twoProd(xs[m], sv.x, p, e);
            e = fmaf(xs[m], sv.y, e);
            twoSum(s, p, s, t1);
            c += t1 + e;
        }
    }
    #pragma unroll
    for (int o = 16; o > 0; o >>= 1) {
        float s2 = __shfl_xor_sync(0xffffffffu, s, o);
        float c2 = __shfl_xor_sync(0xffffffffu, c, o);
        float t1;
        twoSum(s, s2, s, t1);
        c += c2 + t1;
    }
    if (lane == 0) {
        double den = (double)s + (double)c;
        g_rinv[row] = (float)(1.0 / den);
    }
}

// ---------------------------------------------------------------------------
// Kernel 5: OUT = (X @ M) * rinv rowwise.
// grid = (128 row tiles, 2 col tiles). Tile 64x128, 4x8 per thread, j packed
// f32x2. Double-buffered smem, one sync per stage.
// ---------------------------------------------------------------------------
__global__ void __launch_bounds__(256) k_out(const float* __restrict__ X,
                                             float* __restrict__ OUT) {
    __shared__ float SA[2][8][68];
    __shared__ float SB[2][8][128];

    const int row0 = blockIdx.x * 64;
    const int c0   = blockIdx.y * 128;
    const int tx   = threadIdx.x & 15;
    const int ty   = (threadIdx.x >> 4) & 15;

    // loader roles: tid<128 -> SA (X rows, transposed); tid>=128 -> SB (g_M)
    const int ar  = threadIdx.x >> 1;         // 0..63 (valid when tid<128)
    const int ah  = threadIdx.x & 1;
    const int bix = threadIdx.x - 128;        // 0..127 (valid when tid>=128)

    ull T2[4][4];
    #pragma unroll
    for (int i = 0; i < 4; i++)
        #pragma unroll
        for (int j = 0; j < 4; j++) T2[i][j] = 0ull;

    // prologue: stage 0
    if (threadIdx.x < 128) {
        float4 v = *reinterpret_cast<const float4*>(X + (size_t)(row0 + ar) * DDIM + ah * 4);
        SA[0][ah * 4 + 0][ar] = v.x;
        SA[0][ah * 4 + 1][ar] = v.y;
        SA[0][ah * 4 + 2][ar] = v.z;
        SA[0][ah * 4 + 3][ar] = v.w;
    } else {
        #pragma unroll
        for (int q = 0; q < 2; q++) {
            const int fidx = bix + q * 128;
            const int br = fidx >> 5, bs = fidx & 31;
            *reinterpret_cast<float4*>(&SB[0][br][bs * 4]) =
                *reinterpret_cast<const float4*>(&g_M[br * DDIM + c0 + bs * 4]);
        }
    }
    __syncthreads();

    for (int s = 0; s < 32; s++) {
        const int p = s & 1;
        float4 va, vb0, vb1;
        if (s < 31) {
            const int k1 = (s + 1) * 8;
            if (threadIdx.x < 128) {
                va = *reinterpret_cast<const float4*>(X + (size_t)(row0 + ar) * DDIM + k1 + ah * 4);
            } else {
                const int br0 = bix >> 5, bs0 = bix & 31;
                vb0 = *reinterpret_cast<const float4*>(&g_M[(k1 + br0) * DDIM + c0 + bs0 * 4]);
                vb1 = *reinterpret_cast<const float4*>(&g_M[(k1 + br0 + 4) * DDIM + c0 + bs0 * 4]);
            }
        }
        #pragma unroll
        for (int r = 0; r < 8; r++) {
            float4 a  = *reinterpret_cast<const float4*>(&SA[p][r][ty * 4]);
            float4 b0 = *reinterpret_cast<const float4*>(&SB[p][r][tx * 8]);
            float4 b1 = *reinterpret_cast<const float4*>(&SB[p][r][tx * 8 + 4]);
            ull bp[4] = {pack2(b0.x, b0.y), pack2(b0.z, b0.w),
                         pack2(b1.x, b1.y), pack2(b1.z, b1.w)};
            const float aa[4] = {a.x, a.y, a.z, a.w};
            #pragma unroll
            for (int i = 0; i < 4; i++) {
                ull ai = dup2(aa[i]);
                #pragma unroll
                for (int j = 0; j < 4; j++) fma2(T2[i][j], ai, bp[j]);
            }
        }
        if (s < 31) {
            if (threadIdx.x < 128) {
                SA[p ^ 1][ah * 4 + 0][ar] = va.x;
                SA[p ^ 1][ah * 4 + 1][ar] = va.y;
                SA[p ^ 1][ah * 4 + 2][ar] = va.z;
                SA[p ^ 1][ah * 4 + 3][ar] = va.w;
            } else {
                const int br0 = bix >> 5, bs0 = bix & 31;
                *reinterpret_cast<float4*>(&SB[p ^ 1][br0][bs0 * 4]) = vb0;
                *reinterpret_cast<float4*>(&SB[p ^ 1][br0 + 4][bs0 * 4]) = vb1;
            }
        }
        __syncthreads();
    }

    #pragma unroll
    for (int i = 0; i < 4; i++) {
        const int m = row0 + ty * 4 + i;
        const float rv = g_rinv[m];
        float2 p0 = unpack2(T2[i][0]);
        float2 p1 = unpack2(T2[i][1]);
        float2 p2 = unpack2(T2[i][2]);
        float2 p3 = unpack2(T2[i][3]);
        *reinterpret_cast<float4*>(&OUT[(size_t)m * DDIM + c0 + tx * 8]) =
            make_float4(p0.x * rv, p0.y * rv, p1.x * rv, p1.y * rv);
        *reinterpret_cast<float4*>(&OUT[(size_t)m * DDIM + c0 + tx * 8 + 4]) =
            make_float4(p2.x * rv, p2.y * rv, p3.x * rv, p3.y * rv);
    }
}

extern "C" void kernel_launch(void* const* d_in, const int* in_sizes, int n_in,
                              void* d_out, int out_size) {
    (void)in_sizes; (void)n_in; (void)out_size;
    const float* X = (const float*)d_in[0];
    float* OUT     = (float*)d_out;

    k_norm_s<<<SCHUNKS, 256>>>(X);
    k_gram<<<dim3(GCHUNKS, NTILES), 256>>>(X);
    k_reduce<<<160, 256>>>();
    k_rinv<<<1024, 256>>>(X);
    k_out<<<dim3(128, 2), 256>>>(X, OUT);
}